// round 6
// baseline (speedup 1.0000x reference)
#include <cuda_runtime.h>

// B, N, D, L = 32, 1000, 256, 3
#define BB 32
#define NN 1000
#define DD 256
#define LL 3
#define NCH 4
#define ROWS 250                   // rows per (b,c) chunk: 4*250 = 1000
#define TOTAL4 (BB * NN * DD / 4)  // 2,048,000 float4 per output half
#define NCTA (BB * NCH)            // 128 CTAs <= 148 SMs: all co-resident

// Scratch + barrier state (no device allocation allowed)
__device__ float    g_partial[NCTA * DD];
__device__ float    g_v[BB * DD];
__device__ unsigned g_barA;   // monotonic phase counters: never reset,
__device__ unsigned g_barB;   // target = (old/N + 1)*N  -> replay-safe

__device__ __forceinline__ void bar_arrive(unsigned* ctr, bool wait_release) {
    __syncthreads();
    if (threadIdx.x == 0 && threadIdx.y == 0) {
        __threadfence();                       // publish prior writes
        unsigned old = atomicAdd(ctr, 1u);
        if (wait_release) {
            unsigned target = (old / NCTA + 1u) * (unsigned)NCTA;
            while (*(volatile unsigned*)ctr < target) { }
            __threadfence();                   // acquire others' writes
        }
    }
    __syncthreads();
}

__global__ __launch_bounds__(512, 1)
void k_gcn_all(const float* __restrict__ nf,
               const float* __restrict__ Ws,
               const float* __restrict__ bs,
               float* __restrict__ out) {
    const int b = blockIdx.x;      // 0..31
    const int c = blockIdx.y;      // 0..3
    const int x = threadIdx.x;     // 0..63  (float4 column)
    const int y = threadIdx.y;     // 0..7   (row group)
    const int tid = y * 64 + x;    // 0..511

    const float4* __restrict__ nf4 = reinterpret_cast<const float4*>(nf);
    float4* o4 = reinterpret_cast<float4*>(out);
    const float4 z4 = make_float4(0.f, 0.f, 0.f, 0.f);

    // ---------------- Phase 1: reduce 250 rows of batch b -----------------
    {
        const float4* __restrict__ p = nf4 + (size_t)(b * NN + c * ROWS) * 64;
        float4 s0 = z4, s1 = z4;
#pragma unroll
        for (int j = 0; j < 4; j++) {
            float4 a[8];
#pragma unroll
            for (int k = 0; k < 8; k++) {
                const int i = j * 8 + k;
                const int lr = y + 8 * i;           // 0..255
                a[k] = (lr < ROWS) ? p[lr * 64 + x] : z4;
            }
#pragma unroll
            for (int k = 0; k < 8; k += 2) {
                s0.x += a[k].x;   s0.y += a[k].y;   s0.z += a[k].z;   s0.w += a[k].w;
                s1.x += a[k+1].x; s1.y += a[k+1].y; s1.z += a[k+1].z; s1.w += a[k+1].w;
            }
        }
        float4 s = make_float4(s0.x + s1.x, s0.y + s1.y, s0.z + s1.z, s0.w + s1.w);

        __shared__ float4 red[8][64];
        red[y][x] = s;
        __syncthreads();
        if (y < 4) {
            float4 t = red[y][x], u = red[y + 4][x];
            t.x += u.x; t.y += u.y; t.z += u.z; t.w += u.w;
            red[y][x] = t;
        }
        __syncthreads();
        if (y < 2) {
            float4 t = red[y][x], u = red[y + 2][x];
            t.x += u.x; t.y += u.y; t.z += u.z; t.w += u.w;
            red[y][x] = t;
        }
        __syncthreads();
        if (y == 0) {
            float4 t = red[0][x], u = red[1][x];
            t.x += u.x; t.y += u.y; t.z += u.z; t.w += u.w;
            reinterpret_cast<float4*>(g_partial)[(b * NCH + c) * 64 + x] = t;
        }
    }

    // ------------- Barrier A: partials published ---------------------------
    // GEMV CTAs (c==0) must wait; copy CTAs proceed without waiting.
    bar_arrive(&g_barA, c == 0);

    if (c == 0) {
        // ---------- 3 fused 256x256 GEMVs (one CTA per batch) --------------
        __shared__ float sv[DD];
        __shared__ float part[2][DD];
        if (tid < DD) {
            float s = g_partial[(b * NCH + 0) * DD + tid]
                    + g_partial[(b * NCH + 1) * DD + tid]
                    + g_partial[(b * NCH + 2) * DD + tid]
                    + g_partial[(b * NCH + 3) * DD + tid];
            sv[tid] = s * (1.0f / (float)NN);
        }
        __syncthreads();

        const int o = tid & (DD - 1);
        const int g = tid >> 8;            // 0..1, K split 2 x 128
#pragma unroll
        for (int l = 0; l < LL; l++) {
            const float* __restrict__ W = Ws + l * DD * DD;
            float acc = 0.f;
            const int k0 = g * 128;
#pragma unroll 8
            for (int k = k0; k < k0 + 128; k++)
                acc = fmaf(sv[k], W[k * DD + o], acc);   // coalesced, L2-resident
            part[g][o] = acc;
            __syncthreads();
            if (g == 0) {
                float r = part[0][o] + part[1][o] + bs[l * DD + o];
                sv[o] = (l < LL - 1) ? fmaxf(r, 0.f) : r;
            }
            __syncthreads();
        }
        if (tid < DD) g_v[b * DD + tid] = sv[tid];
    } else {
        // ---------- Copy half: out[TOTAL4:2*TOTAL4] = nf (overlaps GEMV) ---
        const int rank = b * 3 + (c - 1);      // 0..95
        const int S = 96 * 512;                // 49152
        for (int i = rank * 512 + tid; i < TOTAL4; i += 4 * S) {
            const int j1 = i + S, j2 = i + 2 * S, j3 = i + 3 * S;
            const float4 a0 = nf4[i];
            const float4 a1 = (j1 < TOTAL4) ? nf4[j1] : z4;
            const float4 a2 = (j2 < TOTAL4) ? nf4[j2] : z4;
            const float4 a3 = (j3 < TOTAL4) ? nf4[j3] : z4;
            __stcs(o4 + TOTAL4 + i, a0);
            if (j1 < TOTAL4) __stcs(o4 + TOTAL4 + j1, a1);
            if (j2 < TOTAL4) __stcs(o4 + TOTAL4 + j2, a2);
            if (j3 < TOTAL4) __stcs(o4 + TOTAL4 + j3, a3);
        }
    }

    // ------------- Barrier B: v published, everyone waits -------------------
    bar_arrive(&g_barB, true);

    // ---------------- Phase 3: add half, all 128 CTAs ----------------------
    {
        const float4* __restrict__ v4 = reinterpret_cast<const float4*>(g_v);
        const int ctaid = b * NCH + c;         // 0..127
        const int S = NCTA * 512;              // 65536
        for (int i = ctaid * 512 + tid; i < TOTAL4; i += 4 * S) {
            const int j1 = i + S, j2 = i + 2 * S, j3 = i + 3 * S;
            const float4 a0 = nf4[i];
            const float4 a1 = (j1 < TOTAL4) ? nf4[j1] : z4;
            const float4 a2 = (j2 < TOTAL4) ? nf4[j2] : z4;
            const float4 a3 = (j3 < TOTAL4) ? nf4[j3] : z4;

#define ADD_STORE(jj, aa)                                                     \
            {                                                                 \
                const int bi = (jj) / (NN * 64);                              \
                const float4 vv = v4[bi * 64 + ((jj) & 63)];                  \
                float4 r;                                                     \
                r.x = (aa).x + vv.x; r.y = (aa).y + vv.y;                     \
                r.z = (aa).z + vv.z; r.w = (aa).w + vv.w;                     \
                __stcs(o4 + (jj), r);                                         \
            }
            ADD_STORE(i, a0)
            if (j1 < TOTAL4) ADD_STORE(j1, a1)
            if (j2 < TOTAL4) ADD_STORE(j2, a2)
            if (j3 < TOTAL4) ADD_STORE(j3, a3)
#undef ADD_STORE
        }
    }
}

extern "C" void kernel_launch(void* const* d_in, const int* in_sizes, int n_in,
                              void* d_out, int out_size) {
    // Inputs in metadata order: x (unused), node_feature, Ws, bs
    const float* nf = (const float*)d_in[1];
    const float* Ws = (const float*)d_in[2];
    const float* bs = (const float*)d_in[3];
    float* out = (float*)d_out;

    dim3 grid(BB, NCH);        // 128 CTAs, all co-resident on 148 SMs
    dim3 block(64, 8);         // 512 threads
    k_gcn_all<<<grid, block>>>(nf, Ws, bs, out);
}